// round 6
// baseline (speedup 1.0000x reference)
#include <cuda_runtime.h>
#include <cstddef>

#define S_LEN  2048
#define NB     4
#define NH     8
#define DKH    64
#define DMODEL 512
#define MROWS  (NB * S_LEN)        // 8192

using ull = unsigned long long;

// ---- scratch (device globals: allocation-free rule) ----
__device__ float g_Qp[NB * NH * S_LEN * DKH];   // [BH][S][dk]
__device__ float g_Kp[NB * NH * S_LEN * DKH];   // [BH][S][dk]
__device__ float g_Vp[NB * NH * S_LEN * DKH];   // [BH][S][dk]
__device__ float g_ctx[MROWS * DMODEL];         // [B,S,D]

// ---- packed fp32 (f32x2) helpers: 2 FMAs per instruction on sm_100+ ----
__device__ __forceinline__ void fma2(ull& d, ull a, ull b) {
    asm("fma.rn.f32x2 %0, %1, %2, %0;" : "+l"(d) : "l"(a), "l"(b));
}
__device__ __forceinline__ ull mul2(ull a, ull b) {
    ull d; asm("mul.rn.f32x2 %0, %1, %2;" : "=l"(d) : "l"(a), "l"(b)); return d;
}
__device__ __forceinline__ ull dup2(float x) {
    ull d; asm("mov.b64 %0, {%1, %1};" : "=l"(d) : "f"(x)); return d;
}
union F2U { ull u; float2 f; };

// ============================================================
// C[i,j] = sum_k A[i,k] * W[j,k]   (y = x @ W^T), fp32 via FMA2.
// 128x128 tile, BK=8, 256 threads, 8x8 microtile (j packed in pairs).
// Asd: A duplicated ([k][2r]=(a,a)) -> broadcast LDS.64 reads.
// Bs : natural -> j-pairs via LDS.128.
// PERMUTE: write C as [BH][S][64] instead of [M,512].
// ============================================================
template <bool PERMUTE>
__global__ void __launch_bounds__(256) gemm_xwt_kernel(
    const float* __restrict__ A, const float* __restrict__ W,
    float* __restrict__ C)
{
    __shared__ __align__(16) float Asd[8][256];
    __shared__ __align__(16) float Bs[8][128];

    const int tid = threadIdx.x;
    const int tx = tid & 15;
    const int ty = tid >> 4;
    const int rowBase = blockIdx.y * 128;
    const int colBase = blockIdx.x * 128;

    const bool isA = tid < 128;
    const int  fr  = tid & 127;
    const float* gp = isA ? (A + (size_t)(rowBase + fr) * DMODEL)
                          : (W + (size_t)(colBase + fr) * DMODEL);

    ull acc[8][4];
#pragma unroll
    for (int i = 0; i < 8; i++)
#pragma unroll
        for (int j = 0; j < 4; j++) acc[i][j] = 0ull;

    float4 v0 = *(const float4*)(gp + 0);
    float4 v1 = *(const float4*)(gp + 4);

    for (int k0 = 0; k0 < DMODEL; k0 += 8) {
        __syncthreads();           // prior-iter readers done before overwrite
        if (isA) {
            *(float2*)&Asd[0][2 * fr] = make_float2(v0.x, v0.x);
            *(float2*)&Asd[1][2 * fr] = make_float2(v0.y, v0.y);
            *(float2*)&Asd[2][2 * fr] = make_float2(v0.z, v0.z);
            *(float2*)&Asd[3][2 * fr] = make_float2(v0.w, v0.w);
            *(float2*)&Asd[4][2 * fr] = make_float2(v1.x, v1.x);
            *(float2*)&Asd[5][2 * fr] = make_float2(v1.y, v1.y);
            *(float2*)&Asd[6][2 * fr] = make_float2(v1.z, v1.z);
            *(float2*)&Asd[7][2 * fr] = make_float2(v1.w, v1.w);
        } else {
            Bs[0][fr] = v0.x; Bs[1][fr] = v0.y; Bs[2][fr] = v0.z; Bs[3][fr] = v0.w;
            Bs[4][fr] = v1.x; Bs[5][fr] = v1.y; Bs[6][fr] = v1.z; Bs[7][fr] = v1.w;
        }
        __syncthreads();

        if (k0 + 8 < DMODEL) {     // prefetch next tile under the compute
            v0 = *(const float4*)(gp + k0 + 8);
            v1 = *(const float4*)(gp + k0 + 12);
        }

#pragma unroll
        for (int k = 0; k < 8; k++) {
            ull ad[8];
#pragma unroll
            for (int i = 0; i < 8; i++)
                ad[i] = *(const ull*)&Asd[k][16 * ty + 2 * i];
            ulonglong2 b01 = *(const ulonglong2*)&Bs[k][8 * tx];
            ulonglong2 b23 = *(const ulonglong2*)&Bs[k][8 * tx + 4];
            ull bp[4] = { b01.x, b01.y, b23.x, b23.y };
#pragma unroll
            for (int i = 0; i < 8; i++)
#pragma unroll
                for (int j = 0; j < 4; j++)
                    fma2(acc[i][j], ad[i], bp[j]);
        }
    }

#pragma unroll
    for (int i = 0; i < 8; i++) {
        const int row = rowBase + 8 * ty + i;
        const int b = row >> 11;         // /2048
        const int s = row & 2047;
#pragma unroll
        for (int j2 = 0; j2 < 4; j2++) {
            F2U u; u.u = acc[i][j2];
            const int col = colBase + 8 * tx + 2 * j2;
            if (PERMUTE) {
                const int h = col >> 6, jj = col & 63;
                *(float2*)&C[(((size_t)(b * NH + h) * S_LEN) + s) * DKH + jj] = u.f;
            } else {
                *(float2*)&C[(size_t)row * DMODEL + col] = u.f;
            }
        }
    }
}

// ============================================================
// Causal flash attention, fp32 FMA2, contraction packed in pairs.
// grid = (32 qtiles, 32 bh), block 256 (16x16), 4x4 microtile.
// All smem tiles 64x64 floats, unpadded, 16B-chunk XOR swizzle:
//   word(r,k) = r*64 + ((((k>>2) ^ (r>>2)) & 15) << 2) + (k & 3)
// -> 16-distinct-row LDS.128 column reads = 2 crossbar cycles.
// qs: Q [row][dk] (pre-scaled); ks: K [key][dk] (reused as P [row][key]);
// vst: V transposed [dk][key] (key contiguous -> FMA2 pairs for PV).
// ============================================================
#define ATTN_SMEM (3 * 64 * 64 * 4)   // 49152 B

__device__ __forceinline__ int swzb(int r, int k4) {   // k4 multiple of 4
    return r * 64 + ((((k4 >> 2) ^ (r >> 2)) & 15) << 2);
}
__device__ __forceinline__ int swz(int r, int k) {
    return swzb(r, k & ~3) + (k & 3);
}

__global__ void __launch_bounds__(256) attn_kernel(
    const float* __restrict__ Qp, const float* __restrict__ Kp,
    const float* __restrict__ Vp, float* __restrict__ ctx)
{
    extern __shared__ float sm[];
    float* qs  = sm;                 // 64*64
    float* ks  = sm + 4096;          // 64*64 (reused as P)
    float* vst = sm + 8192;          // 64*64

    const int tid = threadIdx.x;
    const int tx = tid & 15;
    const int ty = tid >> 4;
    const int bh = blockIdx.y;       // 0..31
    const int qt = blockIdx.x;       // 0..31

    const size_t base = (size_t)bh * S_LEN * DKH;
    const float* Qb = Qp + base + (size_t)qt * 64 * DKH;
    const float* Kb = Kp + base;
    const float* Vb = Vp + base;

    // load Q tile, pre-scaled by 1/sqrt(dk) = 0.125
    for (int e = tid; e < 64 * 16; e += 256) {
        const int r = e >> 4;
        const int c4 = (e & 15) * 4;
        float4 v = *(const float4*)&Qb[r * DKH + c4];
        v.x *= 0.125f; v.y *= 0.125f; v.z *= 0.125f; v.w *= 0.125f;
        *(float4*)&qs[swzb(r, c4)] = v;
    }

    float m[4], l[4];
    ull oacc[4][4];
#pragma unroll
    for (int i = 0; i < 4; i++) {
        m[i] = -1e30f; l[i] = 0.0f;
#pragma unroll
        for (int j = 0; j < 4; j++) oacc[i][j] = 0ull;
    }

    for (int kt = 0; kt <= qt; kt++) {
        __syncthreads();   // prev-iter PV readers done (and Q visible on iter 0)
        for (int e = tid; e < 64 * 16; e += 256) {
            const int r = e >> 4;          // key index within tile
            const int c4 = (e & 15) * 4;   // dk chunk
            float4 kv = *(const float4*)&Kb[(size_t)(kt * 64 + r) * DKH + c4];
            float4 vv = *(const float4*)&Vb[(size_t)(kt * 64 + r) * DKH + c4];
            *(float4*)&ks[swzb(r, c4)] = kv;
            vst[swz(c4 + 0, r)] = vv.x;    // V transposed: [dk][key]
            vst[swz(c4 + 1, r)] = vv.y;
            vst[swz(c4 + 2, r)] = vv.z;
            vst[swz(c4 + 3, r)] = vv.w;
        }
        __syncthreads();

        // S = Qs @ K^T, packed over dk pairs
        ull sacc[4][4];
#pragma unroll
        for (int i = 0; i < 4; i++)
#pragma unroll
            for (int j = 0; j < 4; j++) sacc[i][j] = 0ull;

#pragma unroll 2
        for (int k = 0; k < 64; k += 4) {
            ulonglong2 qa[4], kb[4];
#pragma unroll
            for (int i = 0; i < 4; i++)
                qa[i] = *(const ulonglong2*)&qs[swzb(4 * ty + i, k)];
#pragma unroll
            for (int j = 0; j < 4; j++)
                kb[j] = *(const ulonglong2*)&ks[swzb(4 * tx + j, k)];
#pragma unroll
            for (int i = 0; i < 4; i++)
#pragma unroll
                for (int j = 0; j < 4; j++) {
                    fma2(sacc[i][j], qa[i].x, kb[j].x);
                    fma2(sacc[i][j], qa[i].y, kb[j].y);
                }
        }

        float s[4][4];
#pragma unroll
        for (int i = 0; i < 4; i++)
#pragma unroll
            for (int j = 0; j < 4; j++) {
                F2U u; u.u = sacc[i][j];
                s[i][j] = u.f.x + u.f.y;
            }

        if (kt == qt) {   // diagonal tile: mask cols > rows
#pragma unroll
            for (int i = 0; i < 4; i++)
#pragma unroll
                for (int j = 0; j < 4; j++)
                    if ((4 * tx + j) > (4 * ty + i)) s[i][j] = -1e30f;
        }

        // online softmax (16-lane row groups; xor 1,2,4,8 stay in half-warp)
#pragma unroll
        for (int i = 0; i < 4; i++) {
            float mx = fmaxf(fmaxf(s[i][0], s[i][1]), fmaxf(s[i][2], s[i][3]));
            mx = fmaxf(mx, __shfl_xor_sync(0xffffffffu, mx, 1));
            mx = fmaxf(mx, __shfl_xor_sync(0xffffffffu, mx, 2));
            mx = fmaxf(mx, __shfl_xor_sync(0xffffffffu, mx, 4));
            mx = fmaxf(mx, __shfl_xor_sync(0xffffffffu, mx, 8));
            const float mn = fmaxf(m[i], mx);
            const float al = __expf(m[i] - mn);
            m[i] = mn;
            float rs = 0.0f;
#pragma unroll
            for (int j = 0; j < 4; j++) {
                s[i][j] = __expf(s[i][j] - mn);
                rs += s[i][j];
            }
            rs += __shfl_xor_sync(0xffffffffu, rs, 1);
            rs += __shfl_xor_sync(0xffffffffu, rs, 2);
            rs += __shfl_xor_sync(0xffffffffu, rs, 4);
            rs += __shfl_xor_sync(0xffffffffu, rs, 8);
            l[i] = l[i] * al + rs;
            const ull al2 = dup2(al);
#pragma unroll
            for (int j = 0; j < 4; j++) oacc[i][j] = mul2(oacc[i][j], al2);
        }

        __syncthreads();   // all score-readers of ks done before P overwrites it
#pragma unroll
        for (int i = 0; i < 4; i++)
#pragma unroll
            for (int j = 0; j < 4; j++)
                ks[swz(4 * ty + i, 4 * tx + j)] = s[i][j];
        __syncwarp();      // P rows produced & consumed within one half-warp group

        // O += P @ V, packed over key pairs (vst has key contiguous)
#pragma unroll 2
        for (int k = 0; k < 64; k += 4) {
            ulonglong2 pa[4], vb[4];
#pragma unroll
            for (int i = 0; i < 4; i++)
                pa[i] = *(const ulonglong2*)&ks[swzb(4 * ty + i, k)];
#pragma unroll
            for (int j = 0; j < 4; j++)
                vb[j] = *(const ulonglong2*)&vst[swzb(4 * tx + j, k)];
#pragma unroll
            for (int i = 0; i < 4; i++)
#pragma unroll
                for (int j = 0; j < 4; j++) {
                    fma2(oacc[i][j], pa[i].x, vb[j].x);
                    fma2(oacc[i][j], pa[i].y, vb[j].y);
                }
        }
    }

    // epilogue: ctx[b, s, h*64 + c] = (lo+hi) / l
    const int b = bh >> 3;
    const int h = bh & 7;
#pragma unroll
    for (int i = 0; i < 4; i++) {
        const float inv = 1.0f / l[i];
        const int srow = qt * 64 + 4 * ty + i;
        float o[4];
#pragma unroll
        for (int j = 0; j < 4; j++) {
            F2U u; u.u = oacc[i][j];
            o[j] = (u.f.x + u.f.y) * inv;
        }
        *(float4*)&ctx[((size_t)b * S_LEN + srow) * DMODEL + h * DKH + 4 * tx] =
            make_float4(o[0], o[1], o[2], o[3]);
    }
}

// ============================================================
extern "C" void kernel_launch(void* const* d_in, const int* in_sizes, int n_in,
                              void* d_out, int out_size)
{
    const float* iQ = (const float*)d_in[0];
    const float* iK = (const float*)d_in[1];
    const float* iV = (const float*)d_in[2];
    const float* WQ = (const float*)d_in[3];
    const float* WK = (const float*)d_in[4];
    const float* WV = (const float*)d_in[5];
    const float* WO = (const float*)d_in[6];

    float *Qp, *Kp, *Vp, *Ctx;
    cudaGetSymbolAddress((void**)&Qp, g_Qp);
    cudaGetSymbolAddress((void**)&Kp, g_Kp);
    cudaGetSymbolAddress((void**)&Vp, g_Vp);
    cudaGetSymbolAddress((void**)&Ctx, g_ctx);

    cudaFuncSetAttribute(attn_kernel,
                         cudaFuncAttributeMaxDynamicSharedMemorySize, ATTN_SMEM);

    const dim3 ggrid(DMODEL / 128, MROWS / 128);   // (4, 64)
    gemm_xwt_kernel<true><<<ggrid, 256>>>(iQ, WQ, Qp);
    gemm_xwt_kernel<true><<<ggrid, 256>>>(iK, WK, Kp);
    gemm_xwt_kernel<true><<<ggrid, 256>>>(iV, WV, Vp);

    attn_kernel<<<dim3(S_LEN / 64, NB * NH), 256, ATTN_SMEM>>>(Qp, Kp, Vp, Ctx);

    gemm_xwt_kernel<false><<<ggrid, 256>>>(Ctx, WO, (float*)d_out);
}

// round 10
// speedup vs baseline: 2.3008x; 2.3008x over previous
#include <cuda_runtime.h>
#include <cuda_bf16.h>
#include <cstdint>
#include <cstddef>

#define S_LEN  2048
#define NB     4
#define NH     8
#define DKH    64
#define DMODEL 512
#define MROWS  (NB * S_LEN)        // 8192

// ============================================================
// scratch (device globals: allocation-free rule)
// ============================================================
__device__ float g_Qp[NB * NH * S_LEN * DKH];   // [BH][S][dk] fp32
__device__ float g_Kp[NB * NH * S_LEN * DKH];
__device__ float g_Vp[NB * NH * S_LEN * DKH];
__device__ float g_ctx[MROWS * DMODEL];         // [B,S,D] fp32

__device__ __nv_bfloat16 g_qh[MROWS * DMODEL], g_ql[MROWS * DMODEL];
__device__ __nv_bfloat16 g_kh[MROWS * DMODEL], g_kl[MROWS * DMODEL];
__device__ __nv_bfloat16 g_vh[MROWS * DMODEL], g_vl[MROWS * DMODEL];
__device__ __nv_bfloat16 g_ch[MROWS * DMODEL], g_cl[MROWS * DMODEL];
__device__ __nv_bfloat16 g_wh[4][DMODEL * DMODEL], g_wl[4][DMODEL * DMODEL];

// ============================================================
// helpers (sm_80-class PTX only: ldmatrix + mma.sync -> legal at compute_103)
// ============================================================
__device__ __forceinline__ uint32_t smem_to_u32(const void* p) {
    uint32_t a;
    asm("{ .reg .u64 t; cvta.to.shared.u64 t, %1; cvt.u32.u64 %0, t; }"
        : "=r"(a) : "l"(p));
    return a;
}

#define SW128(bo) ((bo) ^ (((bo) >> 3) & 0x70))

__device__ __forceinline__ void ldm_x4(uint32_t* r, uint32_t addr) {
    asm volatile("ldmatrix.sync.aligned.m8n8.x4.shared.b16 {%0,%1,%2,%3}, [%4];"
                 : "=r"(r[0]), "=r"(r[1]), "=r"(r[2]), "=r"(r[3]) : "r"(addr));
}

__device__ __forceinline__ void mma16816(float* d, const uint32_t* a,
                                         uint32_t b0, uint32_t b1) {
    asm volatile(
        "mma.sync.aligned.m16n8k16.row.col.f32.bf16.bf16.f32 "
        "{%0,%1,%2,%3}, {%4,%5,%6,%7}, {%8,%9}, {%0,%1,%2,%3};"
        : "+f"(d[0]), "+f"(d[1]), "+f"(d[2]), "+f"(d[3])
        : "r"(a[0]), "r"(a[1]), "r"(a[2]), "r"(a[3]), "r"(b0), "r"(b1));
}

// ============================================================
// fp32 -> bf16 hi/lo split (elementwise, float4-vectorized)
// ============================================================
__global__ void __launch_bounds__(256) cvt_hilo(
    const float* __restrict__ x, __nv_bfloat16* __restrict__ hi,
    __nv_bfloat16* __restrict__ lo, int n4)
{
    int i = blockIdx.x * blockDim.x + threadIdx.x;
    if (i >= n4) return;
    float4 v = ((const float4*)x)[i];
    __nv_bfloat16 h0 = __float2bfloat16(v.x), h1 = __float2bfloat16(v.y);
    __nv_bfloat16 h2 = __float2bfloat16(v.z), h3 = __float2bfloat16(v.w);
    __nv_bfloat16 l0 = __float2bfloat16(v.x - __bfloat162float(h0));
    __nv_bfloat16 l1 = __float2bfloat16(v.y - __bfloat162float(h1));
    __nv_bfloat16 l2 = __float2bfloat16(v.z - __bfloat162float(h2));
    __nv_bfloat16 l3 = __float2bfloat16(v.w - __bfloat162float(h3));
    __nv_bfloat162* H = (__nv_bfloat162*)hi;
    __nv_bfloat162* L = (__nv_bfloat162*)lo;
    __nv_bfloat162 p;
    p.x = h0; p.y = h1; H[2 * i]     = p;
    p.x = h2; p.y = h3; H[2 * i + 1] = p;
    p.x = l0; p.y = l1; L[2 * i]     = p;
    p.x = l2; p.y = l3; L[2 * i + 1] = p;
}

// ============================================================
// split-bf16 GEMM via mma.sync (HMMA): C[i,j] = sum_k A[i,k]*B[j,k]
//   = Ah*Bh + Ah*Bl + Al*Bh  (fp32 accumulate)
// CTA tile 128x128, K-chunk 64 (128B SW128 rows), 256 thr / 8 warps,
// warp tile 64x32 (warp grid 2x4), mma m16n8k16, ldmatrix x4 both ops.
// MODE 0: C natural [M,512];  MODE 1: C permuted [BH][S][64].
// ============================================================
#define TCG_SMEM (4 * 16384)     // 65536 B

template <int MODE>
__global__ void __launch_bounds__(256) tc_gemm(
    const __nv_bfloat16* __restrict__ Ah, const __nv_bfloat16* __restrict__ Al,
    const __nv_bfloat16* __restrict__ Bh, const __nv_bfloat16* __restrict__ Bl,
    float* __restrict__ C)
{
    extern __shared__ char smem[];
    const uint32_t sb = smem_to_u32(smem);
    constexpr int SM_AH = 0, SM_AL = 16384, SM_BH = 32768, SM_BL = 49152;

    const int tid = threadIdx.x;
    const int wid = tid >> 5;
    const int lid = tid & 31;
    const int rowBase = blockIdx.y * 128;
    const int colBase = blockIdx.x * 128;

    const int mBase = (wid >> 2) * 64;   // warp row: 0 or 64
    const int nBase = (wid & 3) * 32;    // warp col: 0/32/64/96

    const __nv_bfloat16* gsrc[4] = {
        Ah + (size_t)rowBase * DMODEL, Al + (size_t)rowBase * DMODEL,
        Bh + (size_t)colBase * DMODEL, Bl + (size_t)colBase * DMODEL };
    const int doff[4] = { SM_AH, SM_AL, SM_BH, SM_BL };

    float acc[4][4][4];
#pragma unroll
    for (int mi = 0; mi < 4; mi++)
#pragma unroll
        for (int nj = 0; nj < 4; nj++)
#pragma unroll
            for (int r = 0; r < 4; r++) acc[mi][nj][r] = 0.0f;

    const int lm = lid & 15;             // ldmatrix row within 16
    const int lk = (lid >> 4) * 16;      // ldmatrix k-half byte offset

    for (int kc = 0; kc < DMODEL / 64; kc++) {
        __syncthreads();                 // prior-iter readers done
#pragma unroll
        for (int a = 0; a < 4; a++) {
            const __nv_bfloat16* src = gsrc[a] + kc * 64;
            char* dst = smem + doff[a];
#pragma unroll
            for (int it = 0; it < 4; it++) {          // 1024 16B chunks / 256 thr
                const int e = tid + it * 256;
                const int r = e >> 3, c = e & 7;
                uint4 v = *(const uint4*)(src + (size_t)r * DMODEL + c * 8);
                const uint32_t bo = r * 128 + c * 16;
                *(uint4*)(dst + SW128(bo)) = v;
            }
        }
        __syncthreads();

#pragma unroll
        for (int ks = 0; ks < 4; ks++) {              // 4 x k16 per chunk
            uint32_t a_h[4][4], a_l[4][4], b_h[2][4], b_l[2][4];
#pragma unroll
            for (int mi = 0; mi < 4; mi++) {
                const uint32_t bo = (mBase + mi * 16 + lm) * 128 + ks * 32 + lk;
                ldm_x4(a_h[mi], sb + SM_AH + SW128(bo));
                ldm_x4(a_l[mi], sb + SM_AL + SW128(bo));
            }
#pragma unroll
            for (int np = 0; np < 2; np++) {
                const uint32_t bo = (nBase + np * 16 + lm) * 128 + ks * 32 + lk;
                ldm_x4(b_h[np], sb + SM_BH + SW128(bo));
                ldm_x4(b_l[np], sb + SM_BL + SW128(bo));
            }
#pragma unroll
            for (int mi = 0; mi < 4; mi++)
#pragma unroll
                for (int nj = 0; nj < 4; nj++) {
                    const int np = nj >> 1, sel = nj & 1;
                    mma16816(acc[mi][nj], a_h[mi], b_h[np][sel], b_h[np][sel + 2]);
                    mma16816(acc[mi][nj], a_h[mi], b_l[np][sel], b_l[np][sel + 2]);
                    mma16816(acc[mi][nj], a_l[mi], b_h[np][sel], b_h[np][sel + 2]);
                }
        }
    }

    // epilogue (acc in regs; no smem reuse -> no sync needed)
    const int gr = lid >> 2;             // 0..7
    const int gc = (lid & 3) * 2;        // 0,2,4,6
#pragma unroll
    for (int mi = 0; mi < 4; mi++)
#pragma unroll
        for (int nj = 0; nj < 4; nj++) {
            const int col = colBase + nBase + nj * 8 + gc;
#pragma unroll
            for (int half = 0; half < 2; half++) {
                const int row = rowBase + mBase + mi * 16 + gr + half * 8;
                float* dst;
                if (MODE == 1) {
                    const int b = row >> 11, s = row & 2047;
                    const int h = col >> 6, jj = col & 63;
                    dst = C + (((size_t)(b * NH + h) * S_LEN) + s) * DKH + jj;
                } else {
                    dst = C + (size_t)row * DMODEL + col;
                }
                *(float2*)dst = make_float2(acc[mi][nj][2 * half],
                                            acc[mi][nj][2 * half + 1]);
            }
        }
}

// ============================================================
// Causal flash attention (proven R2 scalar version, 691 us).
// grid = (S/64 qtiles, B*H), block = 256 (16x16), 4x4 microtile.
// ============================================================
#define ATTN_SMEM (3 * 64 * 65 * 4)

__global__ void __launch_bounds__(256) attn_kernel(
    const float* __restrict__ Qp, const float* __restrict__ Kp,
    const float* __restrict__ Vp, float* __restrict__ ctx)
{
    extern __shared__ float sm[];
    float* qs = sm;
    float* ks = sm + 64 * 65;
    float* vs = sm + 2 * 64 * 65;

    const int tid = threadIdx.x;
    const int tx = tid & 15;
    const int ty = tid >> 4;
    const int bh = blockIdx.y;
    const int qt = blockIdx.x;

    const size_t base = (size_t)bh * S_LEN * DKH;
    const float* Qb = Qp + base + (size_t)qt * 64 * DKH;
    const float* Kb = Kp + base;
    const float* Vb = Vp + base;

    for (int e = tid; e < 64 * 16; e += 256) {
        const int r = e >> 4;
        const int c4 = (e & 15) * 4;
        float4 v = *(const float4*)&Qb[r * DKH + c4];
        qs[r * 65 + c4 + 0] = v.x * 0.125f;
        qs[r * 65 + c4 + 1] = v.y * 0.125f;
        qs[r * 65 + c4 + 2] = v.z * 0.125f;
        qs[r * 65 + c4 + 3] = v.w * 0.125f;
    }

    float m[4], l[4], acc[4][4];
#pragma unroll
    for (int i = 0; i < 4; i++) {
        m[i] = -1e30f; l[i] = 0.0f;
#pragma unroll
        for (int j = 0; j < 4; j++) acc[i][j] = 0.0f;
    }

    for (int kt = 0; kt <= qt; kt++) {
        __syncthreads();
        for (int e = tid; e < 64 * 16; e += 256) {
            const int r = e >> 4;
            const int c4 = (e & 15) * 4;
            float4 kv = *(const float4*)&Kb[(size_t)(kt * 64 + r) * DKH + c4];
            float4 vv = *(const float4*)&Vb[(size_t)(kt * 64 + r) * DKH + c4];
            ks[r * 65 + c4 + 0] = kv.x; ks[r * 65 + c4 + 1] = kv.y;
            ks[r * 65 + c4 + 2] = kv.z; ks[r * 65 + c4 + 3] = kv.w;
            vs[r * 65 + c4 + 0] = vv.x; vs[r * 65 + c4 + 1] = vv.y;
            vs[r * 65 + c4 + 2] = vv.z; vs[r * 65 + c4 + 3] = vv.w;
        }
        __syncthreads();

        float s[4][4];
#pragma unroll
        for (int i = 0; i < 4; i++)
#pragma unroll
            for (int j = 0; j < 4; j++) s[i][j] = 0.0f;

#pragma unroll 8
        for (int k = 0; k < 64; k++) {
            float qa[4], kb[4];
#pragma unroll
            for (int i = 0; i < 4; i++) qa[i] = qs[(4 * ty + i) * 65 + k];
#pragma unroll
            for (int j = 0; j < 4; j++) kb[j] = ks[(4 * tx + j) * 65 + k];
#pragma unroll
            for (int i = 0; i < 4; i++)
#pragma unroll
                for (int j = 0; j < 4; j++)
                    s[i][j] += qa[i] * kb[j];
        }

        if (kt == qt) {
#pragma unroll
            for (int i = 0; i < 4; i++)
#pragma unroll
                for (int j = 0; j < 4; j++)
                    if ((4 * tx + j) > (4 * ty + i)) s[i][j] = -1e30f;
        }

#pragma unroll
        for (int i = 0; i < 4; i++) {
            float mx = fmaxf(fmaxf(s[i][0], s[i][1]), fmaxf(s[i][2], s[i][3]));
            mx = fmaxf(mx, __shfl_xor_sync(0xffffffffu, mx, 1));
            mx = fmaxf(mx, __shfl_xor_sync(0xffffffffu, mx, 2));
            mx = fmaxf(mx, __shfl_xor_sync(0xffffffffu, mx, 4));
            mx = fmaxf(mx, __shfl_xor_sync(0xffffffffu, mx, 8));
            const float mn = fmaxf(m[i], mx);
            const float al = __expf(m[i] - mn);
            m[i] = mn;
            float rs = 0.0f;
#pragma unroll
            for (int j = 0; j < 4; j++) {
                s[i][j] = __expf(s[i][j] - mn);
                rs += s[i][j];
            }
            rs += __shfl_xor_sync(0xffffffffu, rs, 1);
            rs += __shfl_xor_sync(0xffffffffu, rs, 2);
            rs += __shfl_xor_sync(0xffffffffu, rs, 4);
            rs += __shfl_xor_sync(0xffffffffu, rs, 8);
            l[i] = l[i] * al + rs;
#pragma unroll
            for (int j = 0; j < 4; j++) acc[i][j] *= al;
        }

        __syncthreads();
#pragma unroll
        for (int i = 0; i < 4; i++)
#pragma unroll
            for (int j = 0; j < 4; j++)
                ks[(4 * ty + i) * 65 + 4 * tx + j] = s[i][j];
        __syncwarp();

#pragma unroll 8
        for (int k = 0; k < 64; k++) {
            float pa[4], vb[4];
#pragma unroll
            for (int i = 0; i < 4; i++) pa[i] = ks[(4 * ty + i) * 65 + k];
#pragma unroll
            for (int j = 0; j < 4; j++) vb[j] = vs[k * 65 + 4 * tx + j];
#pragma unroll
            for (int i = 0; i < 4; i++)
#pragma unroll
                for (int j = 0; j < 4; j++)
                    acc[i][j] += pa[i] * vb[j];
        }
    }

    const int b = bh >> 3;
    const int h = bh & 7;
#pragma unroll
    for (int i = 0; i < 4; i++) {
        const float inv = 1.0f / l[i];
        const int srow = qt * 64 + 4 * ty + i;
        float4 o;
        o.x = acc[i][0] * inv;
        o.y = acc[i][1] * inv;
        o.z = acc[i][2] * inv;
        o.w = acc[i][3] * inv;
        *(float4*)&ctx[((size_t)b * S_LEN + srow) * DMODEL + h * DKH + 4 * tx] = o;
    }
}

// ============================================================
extern "C" void kernel_launch(void* const* d_in, const int* in_sizes, int n_in,
                              void* d_out, int out_size)
{
    const float* iQ = (const float*)d_in[0];
    const float* iK = (const float*)d_in[1];
    const float* iV = (const float*)d_in[2];
    const float* W[4] = { (const float*)d_in[3], (const float*)d_in[4],
                          (const float*)d_in[5], (const float*)d_in[6] };

    float *Qp, *Kp, *Vp, *Ctx;
    cudaGetSymbolAddress((void**)&Qp, g_Qp);
    cudaGetSymbolAddress((void**)&Kp, g_Kp);
    cudaGetSymbolAddress((void**)&Vp, g_Vp);
    cudaGetSymbolAddress((void**)&Ctx, g_ctx);

    __nv_bfloat16 *qh, *ql, *kh, *kl, *vh, *vl, *ch, *cl, *wh, *wl;
    cudaGetSymbolAddress((void**)&qh, g_qh); cudaGetSymbolAddress((void**)&ql, g_ql);
    cudaGetSymbolAddress((void**)&kh, g_kh); cudaGetSymbolAddress((void**)&kl, g_kl);
    cudaGetSymbolAddress((void**)&vh, g_vh); cudaGetSymbolAddress((void**)&vl, g_vl);
    cudaGetSymbolAddress((void**)&ch, g_ch); cudaGetSymbolAddress((void**)&cl, g_cl);
    cudaGetSymbolAddress((void**)&wh, g_wh); cudaGetSymbolAddress((void**)&wl, g_wl);

    cudaFuncSetAttribute(attn_kernel,
                         cudaFuncAttributeMaxDynamicSharedMemorySize, ATTN_SMEM);
    cudaFuncSetAttribute(tc_gemm<0>,
                         cudaFuncAttributeMaxDynamicSharedMemorySize, TCG_SMEM);
    cudaFuncSetAttribute(tc_gemm<1>,
                         cudaFuncAttributeMaxDynamicSharedMemorySize, TCG_SMEM);

    const int nIn4 = MROWS * DMODEL / 4;       // 1,048,576
    const int nW4  = DMODEL * DMODEL / 4;      // 65,536

    // hi/lo splits
    cvt_hilo<<<nIn4 / 256, 256>>>(iQ, qh, ql, nIn4);
    cvt_hilo<<<nIn4 / 256, 256>>>(iK, kh, kl, nIn4);
    cvt_hilo<<<nIn4 / 256, 256>>>(iV, vh, vl, nIn4);
    for (int w = 0; w < 4; w++)
        cvt_hilo<<<nW4 / 256, 256>>>(W[w], wh + (size_t)w * DMODEL * DMODEL,
                                     wl + (size_t)w * DMODEL * DMODEL, nW4);

    // projections (tensor cores, permuted epilogue)
    const dim3 ggrid(DMODEL / 128, MROWS / 128);   // (4, 64)
    tc_gemm<1><<<ggrid, 256, TCG_SMEM>>>(qh, ql,
        wh + 0 * (size_t)DMODEL * DMODEL, wl + 0 * (size_t)DMODEL * DMODEL, Qp);
    tc_gemm<1><<<ggrid, 256, TCG_SMEM>>>(kh, kl,
        wh + 1 * (size_t)DMODEL * DMODEL, wl + 1 * (size_t)DMODEL * DMODEL, Kp);
    tc_gemm<1><<<ggrid, 256, TCG_SMEM>>>(vh, vl,
        wh + 2 * (size_t)DMODEL * DMODEL, wl + 2 * (size_t)DMODEL * DMODEL, Vp);

    // attention (fp32 scalar, proven)
    attn_kernel<<<dim3(S_LEN / 64, NB * NH), 256, ATTN_SMEM>>>(Qp, Kp, Vp, Ctx);

    // output projection
    cvt_hilo<<<nIn4 / 256, 256>>>(Ctx, ch, cl, nIn4);
    tc_gemm<0><<<ggrid, 256, TCG_SMEM>>>(ch, cl,
        wh + 3 * (size_t)DMODEL * DMODEL, wl + 3 * (size_t)DMODEL * DMODEL,
        (float*)d_out);
}

// round 16
// speedup vs baseline: 4.6061x; 2.0020x over previous
#include <cuda_runtime.h>
#include <cuda_bf16.h>
#include <cstdint>
#include <cstddef>

#define S_LEN  2048
#define NB     4
#define NH     8
#define DKH    64
#define DMODEL 512
#define MROWS  (NB * S_LEN)        // 8192
#define BHTOT  (NB * NH)           // 32

// ============================================================
// scratch (device globals: allocation-free rule)
// ============================================================
// input splits (pre-projection)
__device__ __nv_bfloat16 g_qh[MROWS * DMODEL], g_ql[MROWS * DMODEL];
__device__ __nv_bfloat16 g_kh[MROWS * DMODEL], g_kl[MROWS * DMODEL];
__device__ __nv_bfloat16 g_vh[MROWS * DMODEL], g_vl[MROWS * DMODEL];
__device__ __nv_bfloat16 g_wh[4][DMODEL * DMODEL], g_wl[4][DMODEL * DMODEL];
// projected Q/K/V, per-head [BH][S][64], bf16 hi/lo (Q pre-scaled by 1/8)
__device__ __nv_bfloat16 g_Qh[BHTOT * S_LEN * DKH], g_Ql[BHTOT * S_LEN * DKH];
__device__ __nv_bfloat16 g_Kh[BHTOT * S_LEN * DKH], g_Kl[BHTOT * S_LEN * DKH];
__device__ __nv_bfloat16 g_Vh[BHTOT * S_LEN * DKH], g_Vl[BHTOT * S_LEN * DKH];
// attention output (context), natural [M][512], bf16 hi/lo
__device__ __nv_bfloat16 g_ch[MROWS * DMODEL], g_cl[MROWS * DMODEL];

// ============================================================
// helpers (sm_80-class PTX only -> legal at compute_103)
// ============================================================
__device__ __forceinline__ uint32_t smem_to_u32(const void* p) {
    uint32_t a;
    asm("{ .reg .u64 t; cvta.to.shared.u64 t, %1; cvt.u32.u64 %0, t; }"
        : "=r"(a) : "l"(p));
    return a;
}

#define SW128(bo) ((bo) ^ (((bo) >> 3) & 0x70))

__device__ __forceinline__ void ldm_x4(uint32_t* r, uint32_t addr) {
    asm volatile("ldmatrix.sync.aligned.m8n8.x4.shared.b16 {%0,%1,%2,%3}, [%4];"
                 : "=r"(r[0]), "=r"(r[1]), "=r"(r[2]), "=r"(r[3]) : "r"(addr));
}
__device__ __forceinline__ void ldm_x4_t(uint32_t* r, uint32_t addr) {
    asm volatile("ldmatrix.sync.aligned.m8n8.x4.trans.shared.b16 {%0,%1,%2,%3}, [%4];"
                 : "=r"(r[0]), "=r"(r[1]), "=r"(r[2]), "=r"(r[3]) : "r"(addr));
}

__device__ __forceinline__ void mma16816(float* d, const uint32_t* a,
                                         uint32_t b0, uint32_t b1) {
    asm volatile(
        "mma.sync.aligned.m16n8k16.row.col.f32.bf16.bf16.f32 "
        "{%0,%1,%2,%3}, {%4,%5,%6,%7}, {%8,%9}, {%0,%1,%2,%3};"
        : "+f"(d[0]), "+f"(d[1]), "+f"(d[2]), "+f"(d[3])
        : "r"(a[0]), "r"(a[1]), "r"(a[2]), "r"(a[3]), "r"(b0), "r"(b1));
}

__device__ __forceinline__ uint32_t pack_bf16(float lo, float hi) {
    __nv_bfloat162 p = __floats2bfloat162_rn(lo, hi);
    return *reinterpret_cast<uint32_t*>(&p);
}

// ============================================================
// fp32 -> bf16 hi/lo split
// ============================================================
__global__ void __launch_bounds__(256) cvt_hilo(
    const float* __restrict__ x, __nv_bfloat16* __restrict__ hi,
    __nv_bfloat16* __restrict__ lo, int n4)
{
    int i = blockIdx.x * blockDim.x + threadIdx.x;
    if (i >= n4) return;
    float4 v = ((const float4*)x)[i];
    __nv_bfloat16 h0 = __float2bfloat16(v.x), h1 = __float2bfloat16(v.y);
    __nv_bfloat16 h2 = __float2bfloat16(v.z), h3 = __float2bfloat16(v.w);
    __nv_bfloat16 l0 = __float2bfloat16(v.x - __bfloat162float(h0));
    __nv_bfloat16 l1 = __float2bfloat16(v.y - __bfloat162float(h1));
    __nv_bfloat16 l2 = __float2bfloat16(v.z - __bfloat162float(h2));
    __nv_bfloat16 l3 = __float2bfloat16(v.w - __bfloat162float(h3));
    __nv_bfloat162* H = (__nv_bfloat162*)hi;
    __nv_bfloat162* L = (__nv_bfloat162*)lo;
    __nv_bfloat162 p;
    p.x = h0; p.y = h1; H[2 * i]     = p;
    p.x = h2; p.y = h3; H[2 * i + 1] = p;
    p.x = l0; p.y = l1; L[2 * i]     = p;
    p.x = l2; p.y = l3; L[2 * i + 1] = p;
}

// ============================================================
// split-bf16 GEMM via mma.sync: C[i,j] = sum_k A[i,k]*B[j,k]
// MODE 0: fp32 C natural [M,512]
// MODE 1: bf16 hi/lo C permuted [BH][S][64], scaled by `scale`
// ============================================================
#define TCG_SMEM (4 * 16384)     // 65536 B

template <int MODE>
__global__ void __launch_bounds__(256) tc_gemm(
    const __nv_bfloat16* __restrict__ Ah, const __nv_bfloat16* __restrict__ Al,
    const __nv_bfloat16* __restrict__ Bh, const __nv_bfloat16* __restrict__ Bl,
    float* __restrict__ C, __nv_bfloat16* __restrict__ Ch,
    __nv_bfloat16* __restrict__ Cl, float scale)
{
    extern __shared__ char smem[];
    const uint32_t sb = smem_to_u32(smem);
    constexpr int SM_AH = 0, SM_AL = 16384, SM_BH = 32768, SM_BL = 49152;

    const int tid = threadIdx.x;
    const int wid = tid >> 5;
    const int lid = tid & 31;
    const int rowBase = blockIdx.y * 128;
    const int colBase = blockIdx.x * 128;

    const int mBase = (wid >> 2) * 64;
    const int nBase = (wid & 3) * 32;

    const __nv_bfloat16* gsrc[4] = {
        Ah + (size_t)rowBase * DMODEL, Al + (size_t)rowBase * DMODEL,
        Bh + (size_t)colBase * DMODEL, Bl + (size_t)colBase * DMODEL };
    const int doff[4] = { SM_AH, SM_AL, SM_BH, SM_BL };

    float acc[4][4][4];
#pragma unroll
    for (int mi = 0; mi < 4; mi++)
#pragma unroll
        for (int nj = 0; nj < 4; nj++)
#pragma unroll
            for (int r = 0; r < 4; r++) acc[mi][nj][r] = 0.0f;

    const int lm = lid & 15;
    const int lk = (lid >> 4) * 16;

    for (int kc = 0; kc < DMODEL / 64; kc++) {
        __syncthreads();
#pragma unroll
        for (int a = 0; a < 4; a++) {
            const __nv_bfloat16* src = gsrc[a] + kc * 64;
            char* dst = smem + doff[a];
#pragma unroll
            for (int it = 0; it < 4; it++) {
                const int e = tid + it * 256;
                const int r = e >> 3, c = e & 7;
                uint4 v = *(const uint4*)(src + (size_t)r * DMODEL + c * 8);
                const uint32_t bo = r * 128 + c * 16;
                *(uint4*)(dst + SW128(bo)) = v;
            }
        }
        __syncthreads();

#pragma unroll
        for (int ks = 0; ks < 4; ks++) {
            uint32_t a_h[4][4], a_l[4][4], b_h[2][4], b_l[2][4];
#pragma unroll
            for (int mi = 0; mi < 4; mi++) {
                const uint32_t bo = (mBase + mi * 16 + lm) * 128 + ks * 32 + lk;
                ldm_x4(a_h[mi], sb + SM_AH + SW128(bo));
                ldm_x4(a_l[mi], sb + SM_AL + SW128(bo));
            }
#pragma unroll
            for (int np = 0; np < 2; np++) {
                const uint32_t bo = (nBase + np * 16 + lm) * 128 + ks * 32 + lk;
                ldm_x4(b_h[np], sb + SM_BH + SW128(bo));
                ldm_x4(b_l[np], sb + SM_BL + SW128(bo));
            }
#pragma unroll
            for (int mi = 0; mi < 4; mi++)
#pragma unroll
                for (int nj = 0; nj < 4; nj++) {
                    const int np = nj >> 1, sel = nj & 1;
                    mma16816(acc[mi][nj], a_h[mi], b_h[np][sel], b_h[np][sel + 2]);
                    mma16816(acc[mi][nj], a_h[mi], b_l[np][sel], b_l[np][sel + 2]);
                    mma16816(acc[mi][nj], a_l[mi], b_h[np][sel], b_h[np][sel + 2]);
                }
        }
    }

    const int gr = lid >> 2;
    const int gc = (lid & 3) * 2;
#pragma unroll
    for (int mi = 0; mi < 4; mi++)
#pragma unroll
        for (int nj = 0; nj < 4; nj++) {
            const int col = colBase + nBase + nj * 8 + gc;
#pragma unroll
            for (int half = 0; half < 2; half++) {
                const int row = rowBase + mBase + mi * 16 + gr + half * 8;
                if (MODE == 1) {
                    const int b = row >> 11, s = row & 2047;
                    const int h = col >> 6, jj = col & 63;
                    const size_t off =
                        (((size_t)(b * NH + h) * S_LEN) + s) * DKH + jj;
                    float v0 = acc[mi][nj][2 * half] * scale;
                    float v1 = acc[mi][nj][2 * half + 1] * scale;
                    __nv_bfloat16 h0 = __float2bfloat16(v0);
                    __nv_bfloat16 h1 = __float2bfloat16(v1);
                    __nv_bfloat162 hp; hp.x = h0; hp.y = h1;
                    __nv_bfloat162 lp;
                    lp.x = __float2bfloat16(v0 - __bfloat162float(h0));
                    lp.y = __float2bfloat16(v1 - __bfloat162float(h1));
                    *(__nv_bfloat162*)(Ch + off) = hp;
                    *(__nv_bfloat162*)(Cl + off) = lp;
                } else {
                    *(float2*)(C + (size_t)row * DMODEL + col) =
                        make_float2(acc[mi][nj][2 * half],
                                    acc[mi][nj][2 * half + 1]);
                }
            }
        }
}

// ============================================================
// Causal flash attention via mma.sync split-bf16.
// grid = (16 qtiles of 128 rows, 32 bh), block = 256 (8 warps).
// Warp w owns q-rows [w*16, w*16+16). KV tiles of 64 keys.
// Scores: S = Q K^T  (Qh Kh + Qh Kl + Ql Kh), Q pre-scaled by 1/8.
// P built in registers (acc layout == A-frag layout), split hi/lo.
// PV: B-fragments of V^T via ldmatrix.trans on V [key][dk].
// Output: ctx hi/lo bf16, natural [M][512] layout.
// ============================================================
#define QT 128
#define KT 64
// smem: QH 16K | QL 16K | KH 8K | KL 8K | VH 8K | VL 8K = 64K
#define ATTN_SMEM 65536

__global__ void __launch_bounds__(256) attn_mma(
    const __nv_bfloat16* __restrict__ Qh, const __nv_bfloat16* __restrict__ Ql,
    const __nv_bfloat16* __restrict__ Kh, const __nv_bfloat16* __restrict__ Kl,
    const __nv_bfloat16* __restrict__ Vh, const __nv_bfloat16* __restrict__ Vl,
    __nv_bfloat16* __restrict__ Ch, __nv_bfloat16* __restrict__ Cl)
{
    extern __shared__ char smem[];
    const uint32_t sb = smem_to_u32(smem);
    constexpr int SM_QH = 0, SM_QL = 16384;
    constexpr int SM_KH = 32768, SM_KL = 40960, SM_VH = 49152, SM_VL = 57344;

    const int tid = threadIdx.x;
    const int w   = tid >> 5;
    const int lid = tid & 31;
    const int qt  = blockIdx.x;
    const int bh  = blockIdx.y;

    const size_t hbase = (size_t)bh * S_LEN * DKH;
    const int qbase = qt * QT;

    // ---- load Q tile (128 x 64 bf16, hi+lo) into swizzled smem ----
    {
        const __nv_bfloat16* sh = Qh + hbase + (size_t)qbase * DKH;
        const __nv_bfloat16* sl = Ql + hbase + (size_t)qbase * DKH;
#pragma unroll
        for (int it = 0; it < 4; it++) {
            const int e = tid + it * 256;          // 1024 chunks of 16B
            const int r = e >> 3, c = e & 7;
            const uint32_t bo = SW128((uint32_t)(r * 128 + c * 16));
            *(uint4*)(smem + SM_QH + bo) = *(const uint4*)(sh + r * DKH + c * 8);
            *(uint4*)(smem + SM_QL + bo) = *(const uint4*)(sl + r * DKH + c * 8);
        }
    }
    __syncthreads();

    // ---- Q fragments to registers (per warp: rows w*16..w*16+15) ----
    const int lm = lid & 15;
    const int lk = (lid >> 4) * 16;
    uint32_t qf_h[4][4], qf_l[4][4];
#pragma unroll
    for (int ks = 0; ks < 4; ks++) {
        const uint32_t bo = SW128((uint32_t)((w * 16 + lm) * 128 + ks * 32 + lk));
        ldm_x4(qf_h[ks], sb + SM_QH + bo);
        ldm_x4(qf_l[ks], sb + SM_QL + bo);
    }

    const int gr = lid >> 2;              // row within m16 (and +8)
    const int gc = (lid & 3) * 2;         // col pair within n8
    const int row0 = qbase + w * 16 + gr; // global q rows this thread owns
    const int row1 = row0 + 8;

    float oacc[8][4];
#pragma unroll
    for (int t = 0; t < 8; t++)
#pragma unroll
        for (int r = 0; r < 4; r++) oacc[t][r] = 0.0f;
    float m0 = -1e30f, m1 = -1e30f, l0 = 0.0f, l1 = 0.0f;

    const int ktmax = 2 * qt + 1;
    for (int kt = 0; kt <= ktmax; kt++) {
        // ---- load K/V tiles (64 x 64 bf16, hi+lo) ----
        __syncthreads();                  // prior-iter readers done
        {
            const size_t rb = hbase + (size_t)(kt * KT) * DKH;
#pragma unroll
            for (int it = 0; it < 2; it++) {
                const int e = tid + it * 256;     // 512 chunks per buffer
                const int r = e >> 3, c = e & 7;
                const uint32_t bo = SW128((uint32_t)(r * 128 + c * 16));
                const size_t go = rb + r * DKH + c * 8;
                *(uint4*)(smem + SM_KH + bo) = *(const uint4*)(Kh + go);
                *(uint4*)(smem + SM_KL + bo) = *(const uint4*)(Kl + go);
                *(uint4*)(smem + SM_VH + bo) = *(const uint4*)(Vh + go);
                *(uint4*)(smem + SM_VL + bo) = *(const uint4*)(Vl + go);
            }
        }
        __syncthreads();

        // ---- scores: sacc[m16 x n64] = Q K^T (split) ----
        float sacc[8][4];
#pragma unroll
        for (int t = 0; t < 8; t++)
#pragma unroll
            for (int r = 0; r < 4; r++) sacc[t][r] = 0.0f;

#pragma unroll
        for (int ks = 0; ks < 4; ks++) {
            uint32_t kbh[4][4], kbl[4][4];
#pragma unroll
            for (int i = 0; i < 4; i++) {
                const uint32_t bo =
                    SW128((uint32_t)((i * 16 + lm) * 128 + ks * 32 + lk));
                ldm_x4(kbh[i], sb + SM_KH + bo);
                ldm_x4(kbl[i], sb + SM_KL + bo);
            }
#pragma unroll
            for (int t = 0; t < 8; t++) {
                const int i = t >> 1, sel = t & 1;
                mma16816(sacc[t], qf_h[ks], kbh[i][sel], kbh[i][sel + 2]);
                mma16816(sacc[t], qf_h[ks], kbl[i][sel], kbl[i][sel + 2]);
                mma16816(sacc[t], qf_l[ks], kbh[i][sel], kbh[i][sel + 2]);
            }
        }

        // ---- causal mask (only tiles that can intersect the diagonal) ----
        if (kt * KT + KT - 1 > qbase + w * 16) {
#pragma unroll
            for (int t = 0; t < 8; t++) {
                const int c0 = kt * KT + t * 8 + gc;
                if (c0 > row0)     sacc[t][0] = -1e30f;
                if (c0 + 1 > row0) sacc[t][1] = -1e30f;
                if (c0 > row1)     sacc[t][2] = -1e30f;
                if (c0 + 1 > row1) sacc[t][3] = -1e30f;
            }
        }

        // ---- online softmax (rows gr and gr+8; quad = lanes gr*4+0..3) ----
        {
            float mx0 = -1e30f, mx1 = -1e30f;
#pragma unroll
            for (int t = 0; t < 8; t++) {
                mx0 = fmaxf(mx0, fmaxf(sacc[t][0], sacc[t][1]));
                mx1 = fmaxf(mx1, fmaxf(sacc[t][2], sacc[t][3]));
            }
            mx0 = fmaxf(mx0, __shfl_xor_sync(0xffffffffu, mx0, 1));
            mx0 = fmaxf(mx0, __shfl_xor_sync(0xffffffffu, mx0, 2));
            mx1 = fmaxf(mx1, __shfl_xor_sync(0xffffffffu, mx1, 1));
            mx1 = fmaxf(mx1, __shfl_xor_sync(0xffffffffu, mx1, 2));
            const float mn0 = fmaxf(m0, mx0), mn1 = fmaxf(m1, mx1);
            const float al0 = __expf(m0 - mn0), al1 = __expf(m1 - mn1);
            m0 = mn0; m1 = mn1;
            float rs0 = 0.0f, rs1 = 0.0f;
#pragma unroll
            for (int t = 0; t < 8; t++) {
                sacc[t][0] = __expf(sacc[t][0] - mn0);
                sacc[t][1] = __expf(sacc[t][1] - mn0);
                sacc[t][2] = __expf(sacc[t][2] - mn1);
                sacc[t][3] = __expf(sacc[t][3] - mn1);
                rs0 += sacc[t][0] + sacc[t][1];
                rs1 += sacc[t][2] + sacc[t][3];
            }
            rs0 += __shfl_xor_sync(0xffffffffu, rs0, 1);
            rs0 += __shfl_xor_sync(0xffffffffu, rs0, 2);
            rs1 += __shfl_xor_sync(0xffffffffu, rs1, 1);
            rs1 += __shfl_xor_sync(0xffffffffu, rs1, 2);
            l0 = l0 * al0 + rs0;
            l1 = l1 * al1 + rs1;
#pragma unroll
            for (int t = 0; t < 8; t++) {
                oacc[t][0] *= al0; oacc[t][1] *= al0;
                oacc[t][2] *= al1; oacc[t][3] *= al1;
            }
        }

        // ---- PV: O += P V (split), P fragments built in registers ----
#pragma unroll
        for (int t2 = 0; t2 < 4; t2++) {
            // P hi/lo A-fragments from score tiles 2*t2, 2*t2+1
            uint32_t ph[4], pl[4];
            {
                const float* sA = sacc[2 * t2];
                const float* sB = sacc[2 * t2 + 1];
                float hA0 = __bfloat162float(__float2bfloat16(sA[0]));
                float hA1 = __bfloat162float(__float2bfloat16(sA[1]));
                float hA2 = __bfloat162float(__float2bfloat16(sA[2]));
                float hA3 = __bfloat162float(__float2bfloat16(sA[3]));
                float hB0 = __bfloat162float(__float2bfloat16(sB[0]));
                float hB1 = __bfloat162float(__float2bfloat16(sB[1]));
                float hB2 = __bfloat162float(__float2bfloat16(sB[2]));
                float hB3 = __bfloat162float(__float2bfloat16(sB[3]));
                ph[0] = pack_bf16(hA0, hA1);
                ph[1] = pack_bf16(hA2, hA3);
                ph[2] = pack_bf16(hB0, hB1);
                ph[3] = pack_bf16(hB2, hB3);
                pl[0] = pack_bf16(sA[0] - hA0, sA[1] - hA1);
                pl[1] = pack_bf16(sA[2] - hA2, sA[3] - hA3);
                pl[2] = pack_bf16(sB[0] - hB0, sB[1] - hB1);
                pl[3] = pack_bf16(sB[2] - hB2, sB[3] - hB3);
            }
            // V^T B-fragments via ldmatrix.trans: keys 16*t2..+15, all 64 dk
            const int krow = t2 * 16 + (lid & 7) + 8 * ((lid >> 3) & 1);
            const int nby  = 16 * ((lid >> 4) & 1);
            uint32_t vbh[4][4], vbl[4][4];
#pragma unroll
            for (int i = 0; i < 4; i++) {
                const uint32_t bo = SW128((uint32_t)(krow * 128 + i * 32 + nby));
                ldm_x4_t(vbh[i], sb + SM_VH + bo);
                ldm_x4_t(vbl[i], sb + SM_VL + bo);
            }
#pragma unroll
            for (int t = 0; t < 8; t++) {
                const int i = t >> 1, sel = (t & 1) * 2;
                mma16816(oacc[t], ph, vbh[i][sel], vbh[i][sel + 1]);
                mma16816(oacc[t], ph, vbl[i][sel], vbl[i][sel + 1]);
                mma16816(oacc[t], pl, vbh[i][sel], vbh[i][sel + 1]);
            }
        }
    }

    // ---- epilogue: ctx = O / l, hi/lo bf16, natural [M][512] ----
    const int b = bh >> 3, h = bh & 7;
    const float inv0 = 1.0f / l0, inv1 = 1.0f / l1;
    const size_t r0off = ((size_t)b * S_LEN + row0) * DMODEL + h * DKH;
    const size_t r1off = ((size_t)b * S_LEN + row1) * DMODEL + h * DKH;
#pragma unroll
    for (int t = 0; t < 8; t++) {
        const int col = t * 8 + gc;
        float v0 = oacc[t][0] * inv0, v1 = oacc[t][1] * inv0;
        float v2 = oacc[t][2] * inv1, v3 = oacc[t][3] * inv1;
        __nv_bfloat16 h0 = __float2bfloat16(v0), h1 = __float2bfloat16(v1);
        __nv_bfloat16 h2 = __float2bfloat16(v2), h3 = __float2bfloat16(v3);
        __nv_bfloat162 hp0; hp0.x = h0; hp0.y = h1;
        __nv_bfloat162 hp1; hp1.x = h2; hp1.y = h3;
        __nv_bfloat162 lp0, lp1;
        lp0.x = __float2bfloat16(v0 - __bfloat162float(h0));
        lp0.y = __float2bfloat16(v1 - __bfloat162float(h1));
        lp1.x = __float2bfloat16(v2 - __bfloat162float(h2));
        lp1.y = __float2bfloat16(v3 - __bfloat162float(h3));
        *(__nv_bfloat162*)(Ch + r0off + col) = hp0;
        *(__nv_bfloat162*)(Cl + r0off + col) = lp0;
        *(__nv_bfloat162*)(Ch + r1off + col) = hp1;
        *(__nv_bfloat162*)(Cl + r1off + col) = lp1;
    }
}

// ============================================================
extern "C" void kernel_launch(void* const* d_in, const int* in_sizes, int n_in,
                              void* d_out, int out_size)
{
    const float* iQ = (const float*)d_in[0];
    const float* iK = (const float*)d_in[1];
    const float* iV = (const float*)d_in[2];
    const float* W[4] = { (const float*)d_in[3], (const float*)d_in[4],
                          (const float*)d_in[5], (const float*)d_in[6] };

    __nv_bfloat16 *qh, *ql, *kh, *kl, *vh, *vl, *wh, *wl;
    __nv_bfloat16 *Qh, *Ql, *Kh, *Kl, *Vh, *Vl, *ch, *cl;
    cudaGetSymbolAddress((void**)&qh, g_qh); cudaGetSymbolAddress((void**)&ql, g_ql);
    cudaGetSymbolAddress((void**)&kh, g_kh); cudaGetSymbolAddress((void**)&kl, g_kl);
    cudaGetSymbolAddress((void**)&vh, g_vh); cudaGetSymbolAddress((void**)&vl, g_vl);
    cudaGetSymbolAddress((void**)&wh, g_wh); cudaGetSymbolAddress((void**)&wl, g_wl);
    cudaGetSymbolAddress((void**)&Qh, g_Qh); cudaGetSymbolAddress((void**)&Ql, g_Ql);
    cudaGetSymbolAddress((void**)&Kh, g_Kh); cudaGetSymbolAddress((void**)&Kl, g_Kl);
    cudaGetSymbolAddress((void**)&Vh, g_Vh); cudaGetSymbolAddress((void**)&Vl, g_Vl);
    cudaGetSymbolAddress((void**)&ch, g_ch); cudaGetSymbolAddress((void**)&cl, g_cl);

    cudaFuncSetAttribute(tc_gemm<0>,
                         cudaFuncAttributeMaxDynamicSharedMemorySize, TCG_SMEM);
    cudaFuncSetAttribute(tc_gemm<1>,
                         cudaFuncAttributeMaxDynamicSharedMemorySize, TCG_SMEM);
    cudaFuncSetAttribute(attn_mma,
                         cudaFuncAttributeMaxDynamicSharedMemorySize, ATTN_SMEM);

    const int nIn4 = MROWS * DMODEL / 4;
    const int nW4  = DMODEL * DMODEL / 4;

    cvt_hilo<<<nIn4 / 256, 256>>>(iQ, qh, ql, nIn4);
    cvt_hilo<<<nIn4 / 256, 256>>>(iK, kh, kl, nIn4);
    cvt_hilo<<<nIn4 / 256, 256>>>(iV, vh, vl, nIn4);
    for (int w = 0; w < 4; w++)
        cvt_hilo<<<nW4 / 256, 256>>>(W[w], wh + (size_t)w * DMODEL * DMODEL,
                                     wl + (size_t)w * DMODEL * DMODEL, nW4);

    const dim3 ggrid(DMODEL / 128, MROWS / 128);   // (4, 64)
    // Q projection pre-scaled by 1/sqrt(dk) = 0.125
    tc_gemm<1><<<ggrid, 256, TCG_SMEM>>>(qh, ql,
        wh + 0 * (size_t)DMODEL * DMODEL, wl + 0 * (size_t)DMODEL * DMODEL,
        nullptr, Qh, Ql, 0.125f);
    tc_gemm<1><<<ggrid, 256, TCG_SMEM>>>(kh, kl,
        wh + 1 * (size_t)DMODEL * DMODEL, wl + 1 * (size_t)DMODEL * DMODEL,
        nullptr, Kh, Kl, 1.0f);
    tc_gemm<1><<<ggrid, 256, TCG_SMEM>>>(vh, vl,
        wh + 2 * (size_t)DMODEL * DMODEL, wl + 2 * (size_t)DMODEL * DMODEL,
        nullptr, Vh, Vl, 1.0f);

    attn_mma<<<dim3(S_LEN / QT, BHTOT), 256, ATTN_SMEM>>>(
        Qh, Ql, Kh, Kl, Vh, Vl, ch, cl);

    tc_gemm<0><<<ggrid, 256, TCG_SMEM>>>(ch, cl,
        wh + 3 * (size_t)DMODEL * DMODEL, wl + 3 * (size_t)DMODEL * DMODEL,
        (float*)d_out, nullptr, nullptr, 1.0f);
}